// round 3
// baseline (speedup 1.0000x reference)
#include <cuda_runtime.h>

#define NN 50000
#define TT 1000
#define NCL 5
#define TWO_PI_F 6.28318530717958647692f

// ---------------- device scratch ----------------
__device__ float  g_stats[NCL * 13];     // [0]=cnt, [1..4]=amp, [5..8]=cos, [9..12]=sin per cluster
__device__ float  g_cmean_amp[NCL * 4];
__device__ float  g_cmean_ph[NCL * 4];
__device__ float  g_ccnt[NCL];
__device__ float4 g_cosph[NN];
__device__ float4 g_sinph[NN];
__device__ float  g_coeffd[(NN + 1) * 20];   // per row: 10 coeffs, each DUPLICATED (f32x2-ready); +1 row pad for prefetch
__device__ float  g_basis[10 * 1024];        // basis_j over t

// ---------------- f32x2 fma ----------------
__device__ __forceinline__ unsigned long long f32x2_fma(unsigned long long a,
                                                        unsigned long long b,
                                                        unsigned long long c) {
    unsigned long long d;
    asm("fma.rn.f32x2 %0, %1, %2, %3;" : "=l"(d) : "l"(a), "l"(b), "l"(c));
    return d;
}

// ---------------- kernel 1: zero cluster stats ----------------
__global__ void k_zero() {
    int i = threadIdx.x;
    if (i < NCL * 13) g_stats[i] = 0.f;
}

// ---------------- kernel 2: sincos of raw phases + cluster sums (2 threads/node) ----------------
__global__ void k_accum(const float2* __restrict__ amp2, const float2* __restrict__ ph2,
                        const int* __restrict__ labels) {
    __shared__ float sh[NCL * 13];
    int tid = threadIdx.x;
    if (tid < NCL * 13) sh[tid] = 0.f;
    __syncthreads();
    int t = blockIdx.x * blockDim.x + tid;
    int n = t >> 1;
    int q = t & 1;
    if (n < NN) {
        float2 p = ph2[n * 2 + q];
        float2 a = amp2[n * 2 + q];
        float s0, c0, s1, c1;
        sincosf(p.x, &s0, &c0);
        sincosf(p.y, &s1, &c1);
        reinterpret_cast<float2*>(g_cosph)[n * 2 + q] = make_float2(c0, c1);
        reinterpret_cast<float2*>(g_sinph)[n * 2 + q] = make_float2(s0, s1);
        int l = labels[n];
        float* b = &sh[l * 13];
        int h = 2 * q;
        if (q == 0) atomicAdd(&b[0], 1.f);
        atomicAdd(&b[1 + h], a.x);  atomicAdd(&b[2 + h], a.y);
        atomicAdd(&b[5 + h], c0);   atomicAdd(&b[6 + h], c1);
        atomicAdd(&b[9 + h], s0);   atomicAdd(&b[10 + h], s1);
    }
    __syncthreads();
    if (tid < NCL * 13) atomicAdd(&g_stats[tid], sh[tid]);
}

// ---------------- kernel 3: finalize cluster means ----------------
__global__ void k_final() {
    int tid = threadIdx.x;
    if (tid < NCL * 4) {
        int c = tid >> 2, i = tid & 3;
        float cnt = g_stats[c * 13];
        g_cmean_amp[tid] = g_stats[c * 13 + 1 + i] / fmaxf(cnt, 1.f);
        g_cmean_ph[tid]  = atan2f(g_stats[c * 13 + 9 + i], g_stats[c * 13 + 5 + i]);
        if (i == 0) g_ccnt[c] = cnt;
    }
}

// ---------------- kernel 4: message passing, 4 threads per node ----------------
// Lane q of each 4-lane group gathers a subset of edges (all 4 harmonics),
// then a shuffle transpose-reduce leaves lane q with harmonic q's sums.
__device__ __forceinline__ float qred(const float v[4], bool b0, bool b1) {
    float keep = b0 ? v[1] : v[0];
    float send = b0 ? v[0] : v[1];
    keep += __shfl_xor_sync(0xFFFFFFFFu, send, 1);
    float keep2 = b0 ? v[3] : v[2];
    float send2 = b0 ? v[2] : v[3];
    keep2 += __shfl_xor_sync(0xFFFFFFFFu, send2, 1);
    float k3 = b1 ? keep2 : keep;
    float s3 = b1 ? keep : keep2;
    return k3 + __shfl_xor_sync(0xFFFFFFFFu, s3, 2);
}

__global__ void __launch_bounds__(256) k_coeff(
        const float* __restrict__ off, const float* __restrict__ tr,
        const float4* __restrict__ amp4, const float* __restrict__ amps,
        const float* __restrict__ phs,
        const float* __restrict__ lw, const float* __restrict__ rw,
        const int* __restrict__ lidx, const int* __restrict__ ridx,
        const int* __restrict__ labels) {
    int t = blockIdx.x * blockDim.x + threadIdx.x;
    int ng = t >> 2;                 // node (group) id
    int q  = t & 3;                  // lane within group = harmonic id
    bool valid = ng < NN;
    int n = valid ? ng : (NN - 1);   // clamp: whole group clamps together

    float la[4] = {0,0,0,0}, lc[4] = {0,0,0,0}, ls[4] = {0,0,0,0};
    float ra[4] = {0,0,0,0}, rc[4] = {0,0,0,0}, rs[4] = {0,0,0,0};

    // local: lane q takes edge q; lane 0 also takes edge 4
    {
        int base = n * 5;
        int   j = __ldg(&lidx[base + q]);
        float w = __ldg(&lw[base + q]);
        float4 a = __ldg(&amp4[j]);
        float4 c = g_cosph[j];
        float4 s = g_sinph[j];
        la[0]=fmaf(a.x,w,la[0]); la[1]=fmaf(a.y,w,la[1]); la[2]=fmaf(a.z,w,la[2]); la[3]=fmaf(a.w,w,la[3]);
        lc[0]=fmaf(c.x,w,lc[0]); lc[1]=fmaf(c.y,w,lc[1]); lc[2]=fmaf(c.z,w,lc[2]); lc[3]=fmaf(c.w,w,lc[3]);
        ls[0]=fmaf(s.x,w,ls[0]); ls[1]=fmaf(s.y,w,ls[1]); ls[2]=fmaf(s.z,w,ls[2]); ls[3]=fmaf(s.w,w,ls[3]);
        if (q == 0) {
            j = __ldg(&lidx[base + 4]);
            w = __ldg(&lw[base + 4]);
            a = __ldg(&amp4[j]); c = g_cosph[j]; s = g_sinph[j];
            la[0]=fmaf(a.x,w,la[0]); la[1]=fmaf(a.y,w,la[1]); la[2]=fmaf(a.z,w,la[2]); la[3]=fmaf(a.w,w,la[3]);
            lc[0]=fmaf(c.x,w,lc[0]); lc[1]=fmaf(c.y,w,lc[1]); lc[2]=fmaf(c.z,w,lc[2]); lc[3]=fmaf(c.w,w,lc[3]);
            ls[0]=fmaf(s.x,w,ls[0]); ls[1]=fmaf(s.y,w,ls[1]); ls[2]=fmaf(s.z,w,ls[2]); ls[3]=fmaf(s.w,w,ls[3]);
        }
    }
    // regional: lane q takes edges q, q+4, q+8, (q+12 if < 15)
    {
        int base = n * 15;
#pragma unroll
        for (int kk = 0; kk < 4; kk++) {
            int k = q + 4 * kk;
            if (k < 15) {
                int   j = __ldg(&ridx[base + k]);
                float w = __ldg(&rw[base + k]);
                float4 a = __ldg(&amp4[j]);
                float4 c = g_cosph[j];
                float4 s = g_sinph[j];
                ra[0]=fmaf(a.x,w,ra[0]); ra[1]=fmaf(a.y,w,ra[1]); ra[2]=fmaf(a.z,w,ra[2]); ra[3]=fmaf(a.w,w,ra[3]);
                rc[0]=fmaf(c.x,w,rc[0]); rc[1]=fmaf(c.y,w,rc[1]); rc[2]=fmaf(c.z,w,rc[2]); rc[3]=fmaf(c.w,w,rc[3]);
                rs[0]=fmaf(s.x,w,rs[0]); rs[1]=fmaf(s.y,w,rs[1]); rs[2]=fmaf(s.z,w,rs[2]); rs[3]=fmaf(s.w,w,rs[3]);
            }
        }
    }

    bool b0 = (q & 1) != 0, b1 = (q & 2) != 0;
    float LA = qred(la, b0, b1);
    float LC = qred(lc, b0, b1);
    float LS = qred(ls, b0, b1);
    float RA = qred(ra, b0, b1);
    float RC = qred(rc, b0, b1);
    float RS = qred(rs, b0, b1);

    // epilogue: lane q handles harmonic q
    float paq = __ldg(&amps[n * 4 + q]);
    float ppq = __ldg(&phs[n * 4 + q]);
    int   l   = labels[n];
    float cnt = g_ccnt[l];
    bool  big = cnt > 1.f;

    float cluA  = big ? g_cmean_amp[l * 4 + q] : paq;
    float combA = 0.5f * LA + 0.3f * (0.7f * RA) + 0.2f * cluA;
    float amp   = 0.7f * paq + 0.3f * combA;

    float lp    = atan2f(LS, LC);
    float rp    = atan2f(RS, RC);
    float cluP  = big ? g_cmean_ph[l * 4 + q] : ppq;
    float ph    = 0.7f * ppq + 0.3f * (0.5f * lp + 0.3f * rp + 0.2f * cluP);

    float sv, cv;
    sincosf(ph, &sv, &cv);
    float acs = amp * cv;   // multiplies sin-basis
    float asn = amp * sv;   // multiplies cos-basis

    if (valid) {
        float4* dst = reinterpret_cast<float4*>(g_coeffd + (size_t)n * 20);
        dst[1 + q] = make_float4(acs, acs, asn, asn);
        if (q == 0) {
            float o = __ldg(&off[n]);
            float d = __ldg(&tr[n]);
            dst[0] = make_float4(o, o, d, d);
        }
    }
}

// ---------------- kernel 5: basis table over t ----------------
__global__ void k_basis(const float* __restrict__ tv) {
    int t = blockIdx.x * blockDim.x + threadIdx.x;
    if (t >= TT) return;
    float x = tv[t];
    g_basis[0 * 1024 + t] = 1.f;
    g_basis[1 * 1024 + t] = x;
    const float freqs[4] = {4.f, 2.f, 1.f, 0.5f};
#pragma unroll
    for (int i = 0; i < 4; i++) {
        float th = TWO_PI_F * freqs[i] * x;
        float s, c;
        sincosf(th, &s, &c);
        g_basis[(2 + 2 * i) * 1024 + t] = s;
        g_basis[(3 + 2 * i) * 1024 + t] = c;
    }
}

// ---------------- kernel 6: out[n,t] = sum_j coeff[n,j] * basis[j,t] ----------------
#define ROWS_PER_BLK 50

__global__ void __launch_bounds__(256) k_main(float* __restrict__ out) {
    int tid = threadIdx.x;
    if (tid >= 250) return;          // 250 threads x 4 columns = 1000
    int c0 = tid * 4;

    unsigned long long b01[10], b23[10];
#pragma unroll
    for (int j = 0; j < 10; j++) {
        const float* bp = &g_basis[j * 1024 + c0];
        b01[j] = *reinterpret_cast<const unsigned long long*>(bp);
        b23[j] = *reinterpret_cast<const unsigned long long*>(bp + 2);
    }

    int r0 = blockIdx.x * ROWS_PER_BLK;
    int r1 = r0 + ROWS_PER_BLK;
    if (r1 > NN) r1 = NN;

    const ulonglong2* __restrict__ cf =
        reinterpret_cast<const ulonglong2*>(g_coeffd) + (size_t)r0 * 5;

    // prime pipeline
    ulonglong2 c0v = cf[0], c1v = cf[1], c2v = cf[2], c3v = cf[3], c4v = cf[4];

    for (int r = r0; r < r1; ++r) {
        cf += 5;
        // prefetch next row (g_coeffd has +1 row pad, so always in-bounds)
        ulonglong2 n0 = cf[0], n1 = cf[1], n2 = cf[2], n3 = cf[3], n4 = cf[4];

        unsigned long long a01 = 0ull, a23 = 0ull;
        a01 = f32x2_fma(c0v.x, b01[0], a01);  a23 = f32x2_fma(c0v.x, b23[0], a23);
        a01 = f32x2_fma(c0v.y, b01[1], a01);  a23 = f32x2_fma(c0v.y, b23[1], a23);
        a01 = f32x2_fma(c1v.x, b01[2], a01);  a23 = f32x2_fma(c1v.x, b23[2], a23);
        a01 = f32x2_fma(c1v.y, b01[3], a01);  a23 = f32x2_fma(c1v.y, b23[3], a23);
        a01 = f32x2_fma(c2v.x, b01[4], a01);  a23 = f32x2_fma(c2v.x, b23[4], a23);
        a01 = f32x2_fma(c2v.y, b01[5], a01);  a23 = f32x2_fma(c2v.y, b23[5], a23);
        a01 = f32x2_fma(c3v.x, b01[6], a01);  a23 = f32x2_fma(c3v.x, b23[6], a23);
        a01 = f32x2_fma(c3v.y, b01[7], a01);  a23 = f32x2_fma(c3v.y, b23[7], a23);
        a01 = f32x2_fma(c4v.x, b01[8], a01);  a23 = f32x2_fma(c4v.x, b23[8], a23);
        a01 = f32x2_fma(c4v.y, b01[9], a01);  a23 = f32x2_fma(c4v.y, b23[9], a23);

        uint2 u01 = *reinterpret_cast<uint2*>(&a01);
        uint2 u23 = *reinterpret_cast<uint2*>(&a23);
        float4 o = make_float4(__uint_as_float(u01.x), __uint_as_float(u01.y),
                               __uint_as_float(u23.x), __uint_as_float(u23.y));
        *reinterpret_cast<float4*>(out + (size_t)r * TT + c0) = o;

        c0v = n0; c1v = n1; c2v = n2; c3v = n3; c4v = n4;
    }
}

// ---------------- launch ----------------
extern "C" void kernel_launch(void* const* d_in, const int* in_sizes, int n_in,
                              void* d_out, int out_size) {
    const float*  tv     = (const float*)d_in[0];
    const float*  off    = (const float*)d_in[1];
    const float*  tr     = (const float*)d_in[2];
    const float*  amps   = (const float*)d_in[3];
    const float*  phs    = (const float*)d_in[4];
    const float*  lw     = (const float*)d_in[5];
    const float*  rw     = (const float*)d_in[6];
    const int*    lidx   = (const int*)d_in[7];
    const int*    ridx   = (const int*)d_in[8];
    const int*    labels = (const int*)d_in[9];
    float* out = (float*)d_out;

    k_zero<<<1, 96>>>();
    k_accum<<<(2 * NN + 255) / 256, 256>>>((const float2*)amps, (const float2*)phs, labels);
    k_final<<<1, 32>>>();
    k_coeff<<<(4 * NN + 255) / 256, 256>>>(off, tr, (const float4*)amps, amps, phs,
                                           lw, rw, lidx, ridx, labels);
    k_basis<<<(TT + 255) / 256, 256>>>(tv);
    k_main<<<(NN + ROWS_PER_BLK - 1) / ROWS_PER_BLK, 256>>>(out);
}

// round 4
// speedup vs baseline: 1.6465x; 1.6465x over previous
#include <cuda_runtime.h>

#define NN 50000
#define TT 1000
#define NCL 5
#define TWO_PI_F 6.28318530717958647692f

// ---------------- device scratch ----------------
__device__ float g_stats[NCL * 13];     // [0]=cnt, [1..4]=amp, [5..8]=cos, [9..12]=sin
__device__ float g_cmean_amp[NCL * 4];
__device__ float g_cmean_ph[NCL * 4];
__device__ float g_ccnt[NCL];
__device__ float g_pack[NN * 12];       // per node: amp4 | cos4 | sin4  (48B, gather-friendly)
__device__ float g_coeff[NN * 12];      // per node: off,trend,(acs,asn)x4,pad2 (48B)
__device__ float g_basis[10 * 1024];    // basis_j over t

// ---------------- f32x2 helpers ----------------
__device__ __forceinline__ unsigned long long f32x2_fma(unsigned long long a,
                                                        unsigned long long b,
                                                        unsigned long long c) {
    unsigned long long d;
    asm("fma.rn.f32x2 %0, %1, %2, %3;" : "=l"(d) : "l"(a), "l"(b), "l"(c));
    return d;
}
__device__ __forceinline__ unsigned long long pk2(float v) {
    unsigned long long d;
    asm("mov.b64 %0, {%1, %1};" : "=l"(d) : "r"(__float_as_uint(v)));
    return d;
}

// ---------------- kernel 1: zero cluster stats ----------------
__global__ void k_zero() {
    int i = threadIdx.x;
    if (i < NCL * 13) g_stats[i] = 0.f;
}

// ---------------- kernel 2: sincos + pack + cluster sums (2 threads/node) ----------------
__global__ void k_accum(const float2* __restrict__ amp2, const float2* __restrict__ ph2,
                        const int* __restrict__ labels) {
    __shared__ float sh[NCL * 13];
    int tid = threadIdx.x;
    if (tid < NCL * 13) sh[tid] = 0.f;
    __syncthreads();
    int t = blockIdx.x * blockDim.x + tid;
    int n = t >> 1;
    int q = t & 1;                       // handles harmonics (2q, 2q+1)
    if (n < NN) {
        float2 p = ph2[n * 2 + q];
        float2 a = amp2[n * 2 + q];
        float s0, c0, s1, c1;
        sincosf(p.x, &s0, &c0);
        sincosf(p.y, &s1, &c1);
        float* pk = g_pack + (size_t)n * 12;
        *reinterpret_cast<float2*>(pk + 2 * q)     = a;
        *reinterpret_cast<float2*>(pk + 4 + 2 * q) = make_float2(c0, c1);
        *reinterpret_cast<float2*>(pk + 8 + 2 * q) = make_float2(s0, s1);
        int l = labels[n];
        float* b = &sh[l * 13];
        int h = 2 * q;
        if (q == 0) atomicAdd(&b[0], 1.f);
        atomicAdd(&b[1 + h], a.x);  atomicAdd(&b[2 + h], a.y);
        atomicAdd(&b[5 + h], c0);   atomicAdd(&b[6 + h], c1);
        atomicAdd(&b[9 + h], s0);   atomicAdd(&b[10 + h], s1);
    }
    __syncthreads();
    if (tid < NCL * 13) atomicAdd(&g_stats[tid], sh[tid]);
}

// ---------------- kernel 3: finalize cluster means ----------------
__global__ void k_final() {
    int tid = threadIdx.x;
    if (tid < NCL * 4) {
        int c = tid >> 2, i = tid & 3;
        float cnt = g_stats[c * 13];
        g_cmean_amp[tid] = g_stats[c * 13 + 1 + i] / fmaxf(cnt, 1.f);
        g_cmean_ph[tid]  = atan2f(g_stats[c * 13 + 9 + i], g_stats[c * 13 + 5 + i]);
        if (i == 0) g_ccnt[c] = cnt;
    }
}

// ---------------- kernel 4: message passing, 4 threads per node ----------------
__device__ __forceinline__ float qred(const float v[4], bool b0, bool b1) {
    float keep = b0 ? v[1] : v[0];
    float send = b0 ? v[0] : v[1];
    keep += __shfl_xor_sync(0xFFFFFFFFu, send, 1);
    float keep2 = b0 ? v[3] : v[2];
    float send2 = b0 ? v[2] : v[3];
    keep2 += __shfl_xor_sync(0xFFFFFFFFu, send2, 1);
    float k3 = b1 ? keep2 : keep;
    float s3 = b1 ? keep : keep2;
    return k3 + __shfl_xor_sync(0xFFFFFFFFu, s3, 2);
}

__device__ __forceinline__ void edge_acc(int j, float w,
                                         float la[4], float lc[4], float ls[4]) {
    const float4* e = reinterpret_cast<const float4*>(g_pack + (size_t)j * 12);
    float4 a = __ldg(e + 0);
    float4 c = __ldg(e + 1);
    float4 s = __ldg(e + 2);
    la[0]=fmaf(a.x,w,la[0]); la[1]=fmaf(a.y,w,la[1]); la[2]=fmaf(a.z,w,la[2]); la[3]=fmaf(a.w,w,la[3]);
    lc[0]=fmaf(c.x,w,lc[0]); lc[1]=fmaf(c.y,w,lc[1]); lc[2]=fmaf(c.z,w,lc[2]); lc[3]=fmaf(c.w,w,lc[3]);
    ls[0]=fmaf(s.x,w,ls[0]); ls[1]=fmaf(s.y,w,ls[1]); ls[2]=fmaf(s.z,w,ls[2]); ls[3]=fmaf(s.w,w,ls[3]);
}

__global__ void __launch_bounds__(256) k_coeff(
        const float* __restrict__ off, const float* __restrict__ tr,
        const float* __restrict__ amps, const float* __restrict__ phs,
        const float* __restrict__ lw, const float* __restrict__ rw,
        const int* __restrict__ lidx, const int* __restrict__ ridx,
        const int* __restrict__ labels) {
    int t = blockIdx.x * blockDim.x + threadIdx.x;
    int ng = t >> 2;                 // node (group) id
    int q  = t & 3;                  // lane within group = harmonic id
    bool valid = ng < NN;
    int n = valid ? ng : (NN - 1);   // whole 4-lane group clamps together

    float la[4] = {0,0,0,0}, lc[4] = {0,0,0,0}, ls[4] = {0,0,0,0};
    float ra[4] = {0,0,0,0}, rc[4] = {0,0,0,0}, rs[4] = {0,0,0,0};

    // local: lane q takes edge q; lane 0 also takes edge 4
    {
        int base = n * 5;
        edge_acc(__ldg(&lidx[base + q]), __ldg(&lw[base + q]), la, lc, ls);
        if (q == 0)
            edge_acc(__ldg(&lidx[base + 4]), __ldg(&lw[base + 4]), la, lc, ls);
    }
    // regional: lane q takes edges q, q+4, q+8, (q+12 if < 15)
    {
        int base = n * 15;
#pragma unroll
        for (int kk = 0; kk < 4; kk++) {
            int k = q + 4 * kk;
            if (k < 15)
                edge_acc(__ldg(&ridx[base + k]), __ldg(&rw[base + k]), ra, rc, rs);
        }
    }

    bool b0 = (q & 1) != 0, b1 = (q & 2) != 0;
    float LA = qred(la, b0, b1);
    float LC = qred(lc, b0, b1);
    float LS = qred(ls, b0, b1);
    float RA = qred(ra, b0, b1);
    float RC = qred(rc, b0, b1);
    float RS = qred(rs, b0, b1);

    float paq = __ldg(&amps[n * 4 + q]);
    float ppq = __ldg(&phs[n * 4 + q]);
    int   l   = labels[n];
    float cnt = g_ccnt[l];
    bool  big = cnt > 1.f;

    float cluA  = big ? g_cmean_amp[l * 4 + q] : paq;
    float combA = 0.5f * LA + 0.3f * (0.7f * RA) + 0.2f * cluA;
    float amp   = 0.7f * paq + 0.3f * combA;

    float lp    = atan2f(LS, LC);
    float rp    = atan2f(RS, RC);
    float cluP  = big ? g_cmean_ph[l * 4 + q] : ppq;
    float ph    = 0.7f * ppq + 0.3f * (0.5f * lp + 0.3f * rp + 0.2f * cluP);

    float sv, cv;
    sincosf(ph, &sv, &cv);
    float acs = amp * cv;   // multiplies sin-basis
    float asn = amp * sv;   // multiplies cos-basis

    if (valid) {
        float* row = g_coeff + (size_t)n * 12;
        *reinterpret_cast<float2*>(row + 2 + 2 * q) = make_float2(acs, asn);
        if (q == 0) {
            *reinterpret_cast<float2*>(row) = make_float2(__ldg(&off[n]), __ldg(&tr[n]));
            *reinterpret_cast<float2*>(row + 10) = make_float2(0.f, 0.f);
        }
    }
}

// ---------------- kernel 5: basis table over t ----------------
__global__ void k_basis(const float* __restrict__ tv) {
    int t = blockIdx.x * blockDim.x + threadIdx.x;
    if (t >= TT) return;
    float x = tv[t];
    g_basis[0 * 1024 + t] = 1.f;
    g_basis[1 * 1024 + t] = x;
    const float freqs[4] = {4.f, 2.f, 1.f, 0.5f};
#pragma unroll
    for (int i = 0; i < 4; i++) {
        float th = TWO_PI_F * freqs[i] * x;
        float s, c;
        sincosf(th, &s, &c);
        g_basis[(2 + 2 * i) * 1024 + t] = s;
        g_basis[(3 + 2 * i) * 1024 + t] = c;
    }
}

// ---------------- kernel 6: out[n,t] = sum_j coeff[n,j] * basis[j,t] ----------------
// Block = 256 threads, 250 active in the row loop (4 columns each).
// Coeff rows for the block are staged ONCE into shared memory (coalesced),
// then each row costs 3 broadcast LDS.128 + 10 ALU movs + 20 FFMA2 + 1 STG.128.
#define ROWS_PER_BLK 50

__global__ void __launch_bounds__(256) k_main(float* __restrict__ out) {
    __shared__ float4 sco[ROWS_PER_BLK * 3 + 3];
    int tid = threadIdx.x;
    int r0  = blockIdx.x * ROWS_PER_BLK;

    // stage this block's coeff rows into shared (48B/row = 3 float4)
    {
        int gi = r0 * 3 + tid;
        if (tid < ROWS_PER_BLK * 3 && gi < NN * 3)
            sco[tid] = reinterpret_cast<const float4*>(g_coeff)[gi];
    }
    __syncthreads();

    if (tid >= 250) return;           // 250 threads x 4 columns = 1000
    int c0 = tid * 4;

    unsigned long long b01[10], b23[10];
#pragma unroll
    for (int j = 0; j < 10; j++) {
        const float* bp = &g_basis[j * 1024 + c0];
        b01[j] = *reinterpret_cast<const unsigned long long*>(bp);
        b23[j] = *reinterpret_cast<const unsigned long long*>(bp + 2);
    }

    int nr = ROWS_PER_BLK;
    if (r0 + nr > NN) nr = NN - r0;

    for (int rl = 0; rl < nr; ++rl) {
        float4 q0 = sco[rl * 3 + 0];
        float4 q1 = sco[rl * 3 + 1];
        float4 q2 = sco[rl * 3 + 2];

        unsigned long long cd0 = pk2(q0.x), cd1 = pk2(q0.y), cd2 = pk2(q0.z), cd3 = pk2(q0.w);
        unsigned long long cd4 = pk2(q1.x), cd5 = pk2(q1.y), cd6 = pk2(q1.z), cd7 = pk2(q1.w);
        unsigned long long cd8 = pk2(q2.x), cd9 = pk2(q2.y);

        unsigned long long a01 = 0ull, a23 = 0ull;
        a01 = f32x2_fma(cd0, b01[0], a01);  a23 = f32x2_fma(cd0, b23[0], a23);
        a01 = f32x2_fma(cd1, b01[1], a01);  a23 = f32x2_fma(cd1, b23[1], a23);
        a01 = f32x2_fma(cd2, b01[2], a01);  a23 = f32x2_fma(cd2, b23[2], a23);
        a01 = f32x2_fma(cd3, b01[3], a01);  a23 = f32x2_fma(cd3, b23[3], a23);
        a01 = f32x2_fma(cd4, b01[4], a01);  a23 = f32x2_fma(cd4, b23[4], a23);
        a01 = f32x2_fma(cd5, b01[5], a01);  a23 = f32x2_fma(cd5, b23[5], a23);
        a01 = f32x2_fma(cd6, b01[6], a01);  a23 = f32x2_fma(cd6, b23[6], a23);
        a01 = f32x2_fma(cd7, b01[7], a01);  a23 = f32x2_fma(cd7, b23[7], a23);
        a01 = f32x2_fma(cd8, b01[8], a01);  a23 = f32x2_fma(cd8, b23[8], a23);
        a01 = f32x2_fma(cd9, b01[9], a01);  a23 = f32x2_fma(cd9, b23[9], a23);

        uint2 u01 = *reinterpret_cast<uint2*>(&a01);
        uint2 u23 = *reinterpret_cast<uint2*>(&a23);
        float4 o = make_float4(__uint_as_float(u01.x), __uint_as_float(u01.y),
                               __uint_as_float(u23.x), __uint_as_float(u23.y));
        *reinterpret_cast<float4*>(out + (size_t)(r0 + rl) * TT + c0) = o;
    }
}

// ---------------- launch ----------------
extern "C" void kernel_launch(void* const* d_in, const int* in_sizes, int n_in,
                              void* d_out, int out_size) {
    const float*  tv     = (const float*)d_in[0];
    const float*  off    = (const float*)d_in[1];
    const float*  tr     = (const float*)d_in[2];
    const float*  amps   = (const float*)d_in[3];
    const float*  phs    = (const float*)d_in[4];
    const float*  lw     = (const float*)d_in[5];
    const float*  rw     = (const float*)d_in[6];
    const int*    lidx   = (const int*)d_in[7];
    const int*    ridx   = (const int*)d_in[8];
    const int*    labels = (const int*)d_in[9];
    float* out = (float*)d_out;

    k_zero<<<1, 96>>>();
    k_accum<<<(2 * NN + 255) / 256, 256>>>((const float2*)amps, (const float2*)phs, labels);
    k_final<<<1, 32>>>();
    k_coeff<<<(4 * NN + 255) / 256, 256>>>(off, tr, amps, phs, lw, rw, lidx, ridx, labels);
    k_basis<<<(TT + 255) / 256, 256>>>(tv);
    k_main<<<(NN + ROWS_PER_BLK - 1) / ROWS_PER_BLK, 256>>>(out);
}

// round 6
// speedup vs baseline: 2.0721x; 1.2585x over previous
#include <cuda_runtime.h>

#define NN 50000
#define TT 1000
#define NCL 5
#define TWO_PI_F 6.28318530717958647692f

// ---------------- device scratch ----------------
__device__ float  g_stats[NCL * 13];    // [0]=cnt, [1..4]=amp, [5..8]=cos, [9..12]=sin
__device__ float4 g_packn[NN * 4];      // record j: 4 float4 (amp_q, cos_q, sin_q, 0), 64B/node
__device__ float  g_coeff[NN * 12];     // per node: off,tr,(acs,asn)x4,pad2 (48B)
__device__ float  g_basis[10 * 1024];   // basis_j over t

// ---------------- f32x2 helpers ----------------
__device__ __forceinline__ unsigned long long f32x2_fma(unsigned long long a,
                                                        unsigned long long b,
                                                        unsigned long long c) {
    unsigned long long d;
    asm("fma.rn.f32x2 %0, %1, %2, %3;" : "=l"(d) : "l"(a), "l"(b), "l"(c));
    return d;
}
__device__ __forceinline__ unsigned long long pk2(float v) {
    unsigned long long d;
    asm("mov.b64 %0, {%1, %1};" : "=l"(d) : "r"(__float_as_uint(v)));
    return d;
}

// ---------------- kernel 1: init = basis table (blocks 0..3) + zero stats (block 4) ----------------
__global__ void k_init(const float* __restrict__ tv) {
    if (blockIdx.x == 4) {
        int i = threadIdx.x;
        if (i < NCL * 13) g_stats[i] = 0.f;
        return;
    }
    int t = blockIdx.x * 256 + threadIdx.x;
    if (t >= TT) return;
    float x = tv[t];
    g_basis[0 * 1024 + t] = 1.f;
    g_basis[1 * 1024 + t] = x;
    const float freqs[4] = {4.f, 2.f, 1.f, 0.5f};
#pragma unroll
    for (int i = 0; i < 4; i++) {
        float th = TWO_PI_F * freqs[i] * x;
        float s, c;
        sincosf(th, &s, &c);
        g_basis[(2 + 2 * i) * 1024 + t] = s;
        g_basis[(3 + 2 * i) * 1024 + t] = c;
    }
}

// ---------------- kernel 2: sincos + pack records + cluster sums (2 threads/node) ----------------
__global__ void k_accum(const float2* __restrict__ amp2, const float2* __restrict__ ph2,
                        const int* __restrict__ labels) {
    __shared__ float sh[NCL * 13];
    int tid = threadIdx.x;
    if (tid < NCL * 13) sh[tid] = 0.f;
    __syncthreads();
    int t = blockIdx.x * blockDim.x + tid;
    int n = t >> 1;
    int q = t & 1;                       // handles harmonics (2q, 2q+1)
    if (n < NN) {
        float2 p = ph2[n * 2 + q];
        float2 a = amp2[n * 2 + q];
        float s0, c0, s1, c1;
        sincosf(p.x, &s0, &c0);
        sincosf(p.y, &s1, &c1);
        g_packn[n * 4 + 2 * q]     = make_float4(a.x, c0, s0, 0.f);
        g_packn[n * 4 + 2 * q + 1] = make_float4(a.y, c1, s1, 0.f);
        int l = labels[n];
        float* b = &sh[l * 13];
        int h = 2 * q;
        if (q == 0) atomicAdd(&b[0], 1.f);
        atomicAdd(&b[1 + h], a.x);  atomicAdd(&b[2 + h], a.y);
        atomicAdd(&b[5 + h], c0);   atomicAdd(&b[6 + h], c1);
        atomicAdd(&b[9 + h], s0);   atomicAdd(&b[10 + h], s1);
    }
    __syncthreads();
    if (tid < NCL * 13) atomicAdd(&g_stats[tid], sh[tid]);
}

// ---------------- kernel 3: message passing, one thread per (node, harmonic) ----------------
__global__ void __launch_bounds__(256) k_coeff(
        const float* __restrict__ off, const float* __restrict__ tr,
        const float* __restrict__ amps, const float* __restrict__ phs,
        const float* __restrict__ lw, const float* __restrict__ rw,
        const int* __restrict__ lidx, const int* __restrict__ ridx,
        const int* __restrict__ labels) {
    __shared__ float s_ca[NCL * 4], s_cp[NCL * 4], s_cc[NCL];
    int tid = threadIdx.x;
    if (tid < NCL * 4) {
        int c = tid >> 2, i = tid & 3;
        float cnt = g_stats[c * 13];
        s_ca[tid] = g_stats[c * 13 + 1 + i] / fmaxf(cnt, 1.f);
        s_cp[tid] = atan2f(g_stats[c * 13 + 9 + i], g_stats[c * 13 + 5 + i]);
        if (i == 0) s_cc[c] = cnt;
    }
    __syncthreads();

    int t = blockIdx.x * blockDim.x + tid;
    int n = t >> 2;                  // node id
    int q = t & 3;                   // harmonic id
    bool valid = n < NN;
    if (!valid) n = NN - 1;

    float LA = 0.f, LC = 0.f, LS = 0.f;
    {
        int base = n * 5;
#pragma unroll
        for (int e = 0; e < 5; e++) {
            int   j = __ldg(&lidx[base + e]);
            float w = __ldg(&lw[base + e]);
            float4 g = __ldg(&g_packn[j * 4 + q]);
            LA = fmaf(g.x, w, LA);
            LC = fmaf(g.y, w, LC);
            LS = fmaf(g.z, w, LS);
        }
    }
    float RA = 0.f, RC = 0.f, RS = 0.f;
    {
        int base = n * 15;
#pragma unroll
        for (int e = 0; e < 15; e++) {
            int   j = __ldg(&ridx[base + e]);
            float w = __ldg(&rw[base + e]);
            float4 g = __ldg(&g_packn[j * 4 + q]);
            RA = fmaf(g.x, w, RA);
            RC = fmaf(g.y, w, RC);
            RS = fmaf(g.z, w, RS);
        }
    }

    float paq = __ldg(&amps[n * 4 + q]);
    float ppq = __ldg(&phs[n * 4 + q]);
    int   l   = __ldg(&labels[n]);
    float cnt = s_cc[l];
    bool  big = cnt > 1.f;

    float cluA  = big ? s_ca[l * 4 + q] : paq;
    float combA = 0.5f * LA + 0.3f * (0.7f * RA) + 0.2f * cluA;
    float amp   = 0.7f * paq + 0.3f * combA;

    float lp    = atan2f(LS, LC);
    float rp    = atan2f(RS, RC);
    float cluP  = big ? s_cp[l * 4 + q] : ppq;
    float ph    = 0.7f * ppq + 0.3f * (0.5f * lp + 0.3f * rp + 0.2f * cluP);

    float sv, cv;
    sincosf(ph, &sv, &cv);
    float acs = amp * cv;   // multiplies sin-basis
    float asn = amp * sv;   // multiplies cos-basis

    if (valid) {
        float* row = g_coeff + (size_t)n * 12;
        *reinterpret_cast<float2*>(row + 2 + 2 * q) = make_float2(acs, asn);
        if (q == 0)
            *reinterpret_cast<float2*>(row) = make_float2(__ldg(&off[n]), __ldg(&tr[n]));
        if (q == 1)
            *reinterpret_cast<float2*>(row + 10) = make_float2(0.f, 0.f);
    }
}

// ---------------- kernel 4: out[n,t] = sum_j coeff[n,j] * basis[j,t] ----------------
#define ROWS_PER_BLK 50

__global__ void __launch_bounds__(256) k_main(float* __restrict__ out) {
    __shared__ float4 sco[ROWS_PER_BLK * 3 + 3];
    int tid = threadIdx.x;
    int r0  = blockIdx.x * ROWS_PER_BLK;

    // stage this block's coeff rows into shared (48B/row = 3 float4)
    {
        int gi = r0 * 3 + tid;
        if (tid < ROWS_PER_BLK * 3 && gi < NN * 3)
            sco[tid] = reinterpret_cast<const float4*>(g_coeff)[gi];
    }
    __syncthreads();

    if (tid >= 250) return;           // 250 threads x 4 columns = 1000
    int c0 = tid * 4;

    unsigned long long b01[10], b23[10];
#pragma unroll
    for (int j = 0; j < 10; j++) {
        const float* bp = &g_basis[j * 1024 + c0];
        b01[j] = *reinterpret_cast<const unsigned long long*>(bp);
        b23[j] = *reinterpret_cast<const unsigned long long*>(bp + 2);
    }

    int nr = ROWS_PER_BLK;
    if (r0 + nr > NN) nr = NN - r0;

    for (int rl = 0; rl < nr; ++rl) {
        float4 q0 = sco[rl * 3 + 0];
        float4 q1 = sco[rl * 3 + 1];
        float4 q2 = sco[rl * 3 + 2];

        unsigned long long cd0 = pk2(q0.x), cd1 = pk2(q0.y), cd2 = pk2(q0.z), cd3 = pk2(q0.w);
        unsigned long long cd4 = pk2(q1.x), cd5 = pk2(q1.y), cd6 = pk2(q1.z), cd7 = pk2(q1.w);
        unsigned long long cd8 = pk2(q2.x), cd9 = pk2(q2.y);

        unsigned long long a01 = 0ull, a23 = 0ull;
        a01 = f32x2_fma(cd0, b01[0], a01);  a23 = f32x2_fma(cd0, b23[0], a23);
        a01 = f32x2_fma(cd1, b01[1], a01);  a23 = f32x2_fma(cd1, b23[1], a23);
        a01 = f32x2_fma(cd2, b01[2], a01);  a23 = f32x2_fma(cd2, b23[2], a23);
        a01 = f32x2_fma(cd3, b01[3], a01);  a23 = f32x2_fma(cd3, b23[3], a23);
        a01 = f32x2_fma(cd4, b01[4], a01);  a23 = f32x2_fma(cd4, b23[4], a23);
        a01 = f32x2_fma(cd5, b01[5], a01);  a23 = f32x2_fma(cd5, b23[5], a23);
        a01 = f32x2_fma(cd6, b01[6], a01);  a23 = f32x2_fma(cd6, b23[6], a23);
        a01 = f32x2_fma(cd7, b01[7], a01);  a23 = f32x2_fma(cd7, b23[7], a23);
        a01 = f32x2_fma(cd8, b01[8], a01);  a23 = f32x2_fma(cd8, b23[8], a23);
        a01 = f32x2_fma(cd9, b01[9], a01);  a23 = f32x2_fma(cd9, b23[9], a23);

        uint2 u01 = *reinterpret_cast<uint2*>(&a01);
        uint2 u23 = *reinterpret_cast<uint2*>(&a23);
        float4 o = make_float4(__uint_as_float(u01.x), __uint_as_float(u01.y),
                               __uint_as_float(u23.x), __uint_as_float(u23.y));
        // streaming store: output is write-once, keep L2 for basis/coeff
        __stcs(reinterpret_cast<float4*>(out + (size_t)(r0 + rl) * TT + c0), o);
    }
}

// ---------------- launch ----------------
extern "C" void kernel_launch(void* const* d_in, const int* in_sizes, int n_in,
                              void* d_out, int out_size) {
    const float*  tv     = (const float*)d_in[0];
    const float*  off    = (const float*)d_in[1];
    const float*  tr     = (const float*)d_in[2];
    const float*  amps   = (const float*)d_in[3];
    const float*  phs    = (const float*)d_in[4];
    const float*  lw     = (const float*)d_in[5];
    const float*  rw     = (const float*)d_in[6];
    const int*    lidx   = (const int*)d_in[7];
    const int*    ridx   = (const int*)d_in[8];
    const int*    labels = (const int*)d_in[9];
    float* out = (float*)d_out;

    k_init<<<5, 256>>>(tv);
    k_accum<<<(2 * NN + 255) / 256, 256>>>((const float2*)amps, (const float2*)phs, labels);
    k_coeff<<<(4 * NN + 255) / 256, 256>>>(off, tr, amps, phs, lw, rw, lidx, ridx, labels);
    k_main<<<(NN + ROWS_PER_BLK - 1) / ROWS_PER_BLK, 256>>>(out);
}